// round 15
// baseline (speedup 1.0000x reference)
#include <cuda_runtime.h>
#include <cuda_bf16.h>

// ESN: T=2048 steps, N=2048 reservoir, D=128 input.
// out[t] = erf(U[t] + W_res @ out[t-1]) * 1/sqrt(N),  U = input @ W_in^T
#define T_STEPS 2048
#define N_RES   2048
#define D_IN    128
#define GBLK    128          // persistent blocks (1 per SM, all co-resident)
#define ROWS_PER_BLK 16      // N_RES / GBLK
#define NTHREADS 256
#define CPT      8           // columns per thread = N_RES / NTHREADS
#define NPAIR    8           // row pairs per block (f32x2 packs 2 rows)
#define NCOPY    8           // x-row replication factor (16 consumer blocks/copy)
#define INV_SQRT_N 0.022097086912079612f

__device__ float    g_U[T_STEPS * N_RES];        // input projection scratch (16 MB)
__device__ float    g_x8[2 * NCOPY * N_RES];     // replicated x rows, parity slots
__device__ unsigned g_scount;                    // accumulating step counter
__device__ unsigned g_count;                     // init-barrier arrive counter
__device__ unsigned g_epoch;                     // init-barrier epoch (monotonic)

typedef unsigned long long u64;

__device__ __forceinline__ u64 pack2(float lo, float hi) {
    u64 r; asm("mov.b64 %0, {%1,%2};" : "=l"(r) : "f"(lo), "f"(hi)); return r;
}
__device__ __forceinline__ void unpack2(u64 v, float& lo, float& hi) {
    asm("mov.b64 {%0,%1}, %2;" : "=f"(lo), "=f"(hi) : "l"(v));
}
__device__ __forceinline__ void fma2(u64& acc, u64 a, u64 b) {
    asm("fma.rn.f32x2 %0, %1, %2, %0;" : "+l"(acc) : "l"(a), "l"(b));
}
__device__ __forceinline__ u64 add2(u64 a, u64 b) {
    u64 r; asm("add.rn.f32x2 %0, %1, %2;" : "=l"(r) : "l"(a), "l"(b)); return r;
}
__device__ __forceinline__ u64 shfl_xor64(u64 v, int m) {
    unsigned lo = (unsigned)v, hi = (unsigned)(v >> 32);
    lo = __shfl_xor_sync(0xffffffffu, lo, m);
    hi = __shfl_xor_sync(0xffffffffu, hi, m);
    return ((u64)hi << 32) | (u64)lo;
}
__device__ __forceinline__ unsigned ldrelax(const unsigned* p) {
    unsigned v;
    asm volatile("ld.relaxed.gpu.global.u32 %0, [%1];" : "=r"(v) : "l"(p) : "memory");
    return v;
}

// One-time grid barrier at kernel start (epoch + counter-base agreement).
__device__ __forceinline__ void grid_barrier(int tid, unsigned target) {
    __syncthreads();
    if (tid == 0) {
        unsigned prev;
        asm volatile("atom.release.gpu.global.add.u32 %0, [%1], %2;"
                     : "=r"(prev) : "l"(&g_count), "r"(1u) : "memory");
        if (prev == (unsigned)(GBLK - 1)) {
            asm volatile("st.relaxed.gpu.global.u32 [%0], %1;"
                         :: "l"(&g_count), "r"(0u) : "memory");
            asm volatile("st.release.gpu.global.u32 [%0], %1;"
                         :: "l"(&g_epoch), "r"(target) : "memory");
        } else {
            unsigned cur;
            do {
                asm volatile("ld.acquire.gpu.global.u32 %0, [%1];"
                             : "=r"(cur) : "l"(&g_epoch) : "memory");
            } while (cur != target);
        }
    }
    __syncthreads();
}

// ---------------------------------------------------------------------------
// Kernel 1: U[t][n] = sum_d input[t][d] * W_in[n][d]   (2048 x 2048 x 128)
// 64x64 output tile, 4x4 register micro-tile, K chunked 2x64, transposed smem.
// ---------------------------------------------------------------------------
__global__ void __launch_bounds__(256) u_gemm_kernel(
    const float* __restrict__ inp, const float* __restrict__ win)
{
    __shared__ float As[64][68];   // As[k][m] = inp[t0+m][kc+k]
    __shared__ float Bs[64][68];   // Bs[k][n] = win[n0+n][kc+k]
    const int tid = threadIdx.x;
    const int t0 = blockIdx.y * 64;
    const int n0 = blockIdx.x * 64;
    const int tx = tid & 15, ty = tid >> 4;

    float acc[4][4] = {};

    #pragma unroll
    for (int kc = 0; kc < D_IN; kc += 64) {
        __syncthreads();   // protect smem from previous chunk's readers
        #pragma unroll
        for (int i = 0; i < 4; i++) {
            int fi = tid + i * 256;       // 0..1023 float4 slots
            int m  = fi >> 4;             // 0..63
            int k4 = (fi & 15) << 2;      // 0..60
            float4 va = *(const float4*)(inp + (t0 + m) * D_IN + kc + k4);
            As[k4][m] = va.x; As[k4 + 1][m] = va.y; As[k4 + 2][m] = va.z; As[k4 + 3][m] = va.w;
            float4 vb = *(const float4*)(win + (n0 + m) * D_IN + kc + k4);
            Bs[k4][m] = vb.x; Bs[k4 + 1][m] = vb.y; Bs[k4 + 2][m] = vb.z; Bs[k4 + 3][m] = vb.w;
        }
        __syncthreads();

        #pragma unroll 16
        for (int k = 0; k < 64; k++) {
            float4 a = *(const float4*)(&As[k][4 * ty]);
            float4 b = *(const float4*)(&Bs[k][4 * tx]);
            acc[0][0] = fmaf(a.x, b.x, acc[0][0]); acc[0][1] = fmaf(a.x, b.y, acc[0][1]);
            acc[0][2] = fmaf(a.x, b.z, acc[0][2]); acc[0][3] = fmaf(a.x, b.w, acc[0][3]);
            acc[1][0] = fmaf(a.y, b.x, acc[1][0]); acc[1][1] = fmaf(a.y, b.y, acc[1][1]);
            acc[1][2] = fmaf(a.y, b.z, acc[1][2]); acc[1][3] = fmaf(a.y, b.w, acc[1][3]);
            acc[2][0] = fmaf(a.z, b.x, acc[2][0]); acc[2][1] = fmaf(a.z, b.y, acc[2][1]);
            acc[2][2] = fmaf(a.z, b.z, acc[2][2]); acc[2][3] = fmaf(a.z, b.w, acc[2][3]);
            acc[3][0] = fmaf(a.w, b.x, acc[3][0]); acc[3][1] = fmaf(a.w, b.y, acc[3][1]);
            acc[3][2] = fmaf(a.w, b.z, acc[3][2]); acc[3][3] = fmaf(a.w, b.w, acc[3][3]);
        }
    }

    #pragma unroll
    for (int i = 0; i < 4; i++) {
        float4 v = make_float4(acc[i][0], acc[i][1], acc[i][2], acc[i][3]);
        *(float4*)(g_U + (t0 + 4 * ty + i) * N_RES + n0 + 4 * tx) = v;
    }
}

// ---------------------------------------------------------------------------
// Kernel 2: persistent recurrence == R14's proven kernel with two changes:
//  (1) tid0 detection uses a DEPTH-2 pipelined ld.relaxed probe (2 loads in
//      flight -> counter sampled every ~RT/2) + fence.acq_rel.gpu on success.
//      Ordering correctness of relaxed-probe+fence proven by R12/R13 passes;
//      depth 2 keeps probe traffic at 2x R8 (R13's depth-8 melted the LTS).
//  (2) publish path: every lane already holds the full dot pair after the
//      butterfly, so lanes 0..7 each compute BOTH erfs and store their own
//      x8 copy directly — the two cross-lane shfl broadcasts are deleted.
// Sync topology remains R8's measured optimum: 128 arrivals/step, 128
// pollers chip-wide, all other warps parked at bar.sync.
// ---------------------------------------------------------------------------
__global__ void __launch_bounds__(NTHREADS, 1) esn_recur_kernel(
    const float* __restrict__ wres, float* __restrict__ out)
{
    __shared__ u64 red[NPAIR * NTHREADS];   // 16 KB reduction staging
    __shared__ unsigned s_cbase;

    const int tid = threadIdx.x;
    const int bid = blockIdx.x;
    const int r0  = bid * ROWS_PER_BLK;
    const int c0  = tid * CPT;
    const int wp  = tid >> 5, ln = tid & 31;
    const int mycopy = bid >> 4;            // 16 blocks share each copy

    // Load W_res slice: w[p][c] = {W[r0+2p][c0+c], W[r0+2p+1][c0+c]}
    u64 w[NPAIR][CPT];
    #pragma unroll
    for (int p = 0; p < NPAIR; p++) {
        const float4* ra = (const float4*)(wres + (r0 + 2 * p)     * N_RES + c0);
        const float4* rb = (const float4*)(wres + (r0 + 2 * p + 1) * N_RES + c0);
        float4 a0 = ra[0], a1 = ra[1];
        float4 b0 = rb[0], b1 = rb[1];
        w[p][0] = pack2(a0.x, b0.x); w[p][1] = pack2(a0.y, b0.y);
        w[p][2] = pack2(a0.z, b0.z); w[p][3] = pack2(a0.w, b0.w);
        w[p][4] = pack2(a1.x, b1.x); w[p][5] = pack2(a1.y, b1.y);
        w[p][6] = pack2(a1.z, b1.z); w[p][7] = pack2(a1.w, b1.w);
    }

    // Snapshot the quiescent step-counter; init barrier ensures agreement
    // before any arrival.
    if (tid == 0) {
        unsigned c;
        asm volatile("ld.relaxed.gpu.global.u32 %0, [%1];" : "=r"(c) : "l"(&g_scount) : "memory");
        s_cbase = c;
    }
    unsigned e0;
    asm volatile("ld.acquire.gpu.global.u32 %0, [%1];" : "=r"(e0) : "l"(&g_epoch) : "memory");
    grid_barrier(tid, e0 + 1);
    const unsigned cbase = s_cbase;

    // Step 0: lanes 0..7 each compute both row values; lane ln stores copy ln.
    {
        if (ln < NCOPY) {
            float v0 = erff(g_U[r0 + 2 * wp])     * INV_SQRT_N;
            float v1 = erff(g_U[r0 + 2 * wp + 1]) * INV_SQRT_N;
            u64 pair = pack2(v0, v1);
            *(u64*)(g_x8 + ln * N_RES + r0 + 2 * wp) = pair;   // slot 0
            if (ln == 0)
                *(u64*)(out + r0 + 2 * wp) = pair;
        }
    }
    __syncthreads();   // all stores happen-before tid0's release-arrival
    if (tid == 0)
        asm volatile("red.release.gpu.global.add.u32 [%0], %1;"
                     :: "l"(&g_scount), "r"(1u) : "memory");

    #pragma unroll 1
    for (int t = 1; t < T_STEPS; t++) {
        // Prefetch U[t] for my rows (lanes 0..7, broadcast addresses).
        float u0 = 0.f, u1 = 0.f;
        if (ln < NCOPY) {
            u0 = __ldg(&g_U[t * N_RES + r0 + 2 * wp]);
            u1 = __ldg(&g_U[t * N_RES + r0 + 2 * wp + 1]);
        }

        // Depth-2 pipelined probe: sample every ~RT/2, fence on success.
        if (tid == 0) {
            const unsigned tgt = cbase + (unsigned)(GBLK * t);
            unsigned p0 = ldrelax(&g_scount);
            unsigned p1 = ldrelax(&g_scount);
            while ((int)(p0 - tgt) < 0) {
                p0 = p1;
                p1 = ldrelax(&g_scount);
            }
            asm volatile("fence.acq_rel.gpu;" ::: "memory");
        }
        __syncthreads();   // fence happens-before all lanes' loads

        // Load my 8 x values from MY copy of the previous x row (L1 bypass).
        const float4* xp = (const float4*)(g_x8 + ((t - 1) & 1) * (NCOPY * N_RES)
                                                + mycopy * N_RES + c0);
        float4 xv0 = __ldcg(xp);
        float4 xv1 = __ldcg(xp + 1);
        u64 xx[CPT];
        xx[0] = pack2(xv0.x, xv0.x); xx[1] = pack2(xv0.y, xv0.y);
        xx[2] = pack2(xv0.z, xv0.z); xx[3] = pack2(xv0.w, xv0.w);
        xx[4] = pack2(xv1.x, xv1.x); xx[5] = pack2(xv1.y, xv1.y);
        xx[6] = pack2(xv1.z, xv1.z); xx[7] = pack2(xv1.w, xv1.w);

        u64 acc[NPAIR];
        #pragma unroll
        for (int p = 0; p < NPAIR; p++) acc[p] = 0ULL;
        #pragma unroll
        for (int c = 0; c < CPT; c++) {
            #pragma unroll
            for (int p = 0; p < NPAIR; p++) fma2(acc[p], w[p][c], xx[c]);
        }

        // Stage partials; warp wp reduces row-pair wp across 256 threads.
        #pragma unroll
        for (int p = 0; p < NPAIR; p++) red[p * NTHREADS + tid] = acc[p];
        __syncthreads();

        u64 s = red[wp * NTHREADS + ln];
        #pragma unroll
        for (int k = 1; k < 8; k++) s = add2(s, red[wp * NTHREADS + ln + 32 * k]);
        #pragma unroll
        for (int m = 16; m >= 1; m >>= 1) s = add2(s, shfl_xor64(s, m));
        // Every lane now holds the full {row 2wp, row 2wp+1} dot-product pair.

        // Lanes 0..7 each compute BOTH erfs (redundant, parallel across lanes)
        // and store their own x8 copy — no cross-lane shfl on the publish path.
        if (ln < NCOPY) {
            float lo, hi; unpack2(s, lo, hi);
            float v0 = erff(u0 + lo) * INV_SQRT_N;
            float v1 = erff(u1 + hi) * INV_SQRT_N;
            u64 pair = pack2(v0, v1);
            *(u64*)(g_x8 + (t & 1) * (NCOPY * N_RES) + ln * N_RES + r0 + 2 * wp) = pair;
            if (ln == 0)
                *(u64*)(out + t * N_RES + r0 + 2 * wp) = pair;
        }
        __syncthreads();   // all stores done + red[] safe; HB to tid0 arrival

        if (tid == 0)
            asm volatile("red.release.gpu.global.add.u32 [%0], %1;"
                         :: "l"(&g_scount), "r"(1u) : "memory");
    }
}

// ---------------------------------------------------------------------------
extern "C" void kernel_launch(void* const* d_in, const int* in_sizes, int n_in,
                              void* d_out, int out_size)
{
    const float* input = (const float*)d_in[0];   // (2048, 128)
    const float* w_in  = (const float*)d_in[1];   // (2048, 128)
    const float* w_res = (const float*)d_in[2];   // (2048, 2048)
    float* out = (float*)d_out;                   // (2048, 2048)

    u_gemm_kernel<<<dim3(N_RES / 64, T_STEPS / 64), 256>>>(input, w_in);
    esn_recur_kernel<<<GBLK, NTHREADS>>>(w_res, out);
}

// round 16
// speedup vs baseline: 1.2537x; 1.2537x over previous
#include <cuda_runtime.h>
#include <cuda_bf16.h>

// ESN: T=2048 steps, N=2048 reservoir, D=128 input.
// out[t] = erf(U[t] + W_res @ out[t-1]) * 1/sqrt(N),  U = input @ W_in^T
#define T_STEPS 2048
#define N_RES   2048
#define D_IN    128
#define GBLK    128          // persistent blocks (1 per SM, all co-resident)
#define ROWS_PER_BLK 16      // N_RES / GBLK
#define NTHREADS 256
#define CPT      8           // columns per thread = N_RES / NTHREADS
#define NPAIR    8           // row pairs per block (f32x2 packs 2 rows)
#define NCOPY    8           // x-row replication factor (16 consumer blocks/copy)
#define INV_SQRT_N 0.022097086912079612f

__device__ float    g_U[T_STEPS * N_RES];        // input projection scratch (16 MB)
__device__ float    g_x8[2 * NCOPY * N_RES];     // replicated x rows, parity slots
__device__ unsigned g_scount;                    // accumulating step counter
__device__ unsigned g_count;                     // init-barrier arrive counter
__device__ unsigned g_epoch;                     // init-barrier epoch (monotonic)

typedef unsigned long long u64;

__device__ __forceinline__ u64 pack2(float lo, float hi) {
    u64 r; asm("mov.b64 %0, {%1,%2};" : "=l"(r) : "f"(lo), "f"(hi)); return r;
}
__device__ __forceinline__ void unpack2(u64 v, float& lo, float& hi) {
    asm("mov.b64 {%0,%1}, %2;" : "=f"(lo), "=f"(hi) : "l"(v));
}
__device__ __forceinline__ void fma2(u64& acc, u64 a, u64 b) {
    asm("fma.rn.f32x2 %0, %1, %2, %0;" : "+l"(acc) : "l"(a), "l"(b));
}
__device__ __forceinline__ u64 add2(u64 a, u64 b) {
    u64 r; asm("add.rn.f32x2 %0, %1, %2;" : "=l"(r) : "l"(a), "l"(b)); return r;
}
__device__ __forceinline__ u64 shfl_xor64(u64 v, int m) {
    unsigned lo = (unsigned)v, hi = (unsigned)(v >> 32);
    lo = __shfl_xor_sync(0xffffffffu, lo, m);
    hi = __shfl_xor_sync(0xffffffffu, hi, m);
    return ((u64)hi << 32) | (u64)lo;
}

// One-time grid barrier at kernel start (epoch + counter-base agreement).
__device__ __forceinline__ void grid_barrier(int tid, unsigned target) {
    __syncthreads();
    if (tid == 0) {
        unsigned prev;
        asm volatile("atom.release.gpu.global.add.u32 %0, [%1], %2;"
                     : "=r"(prev) : "l"(&g_count), "r"(1u) : "memory");
        if (prev == (unsigned)(GBLK - 1)) {
            asm volatile("st.relaxed.gpu.global.u32 [%0], %1;"
                         :: "l"(&g_count), "r"(0u) : "memory");
            asm volatile("st.release.gpu.global.u32 [%0], %1;"
                         :: "l"(&g_epoch), "r"(target) : "memory");
        } else {
            unsigned cur;
            do {
                asm volatile("ld.acquire.gpu.global.u32 %0, [%1];"
                             : "=r"(cur) : "l"(&g_epoch) : "memory");
            } while (cur != target);
        }
    }
    __syncthreads();
}

// ---------------------------------------------------------------------------
// Kernel 1: U[t][n] = sum_d input[t][d] * W_in[n][d]   (2048 x 2048 x 128)
// 64x64 output tile, 4x4 register micro-tile, K chunked 2x64, transposed smem.
// ---------------------------------------------------------------------------
__global__ void __launch_bounds__(256) u_gemm_kernel(
    const float* __restrict__ inp, const float* __restrict__ win)
{
    __shared__ float As[64][68];   // As[k][m] = inp[t0+m][kc+k]
    __shared__ float Bs[64][68];   // Bs[k][n] = win[n0+n][kc+k]
    const int tid = threadIdx.x;
    const int t0 = blockIdx.y * 64;
    const int n0 = blockIdx.x * 64;
    const int tx = tid & 15, ty = tid >> 4;

    float acc[4][4] = {};

    #pragma unroll
    for (int kc = 0; kc < D_IN; kc += 64) {
        __syncthreads();   // protect smem from previous chunk's readers
        #pragma unroll
        for (int i = 0; i < 4; i++) {
            int fi = tid + i * 256;       // 0..1023 float4 slots
            int m  = fi >> 4;             // 0..63
            int k4 = (fi & 15) << 2;      // 0..60
            float4 va = *(const float4*)(inp + (t0 + m) * D_IN + kc + k4);
            As[k4][m] = va.x; As[k4 + 1][m] = va.y; As[k4 + 2][m] = va.z; As[k4 + 3][m] = va.w;
            float4 vb = *(const float4*)(win + (n0 + m) * D_IN + kc + k4);
            Bs[k4][m] = vb.x; Bs[k4 + 1][m] = vb.y; Bs[k4 + 2][m] = vb.z; Bs[k4 + 3][m] = vb.w;
        }
        __syncthreads();

        #pragma unroll 16
        for (int k = 0; k < 64; k++) {
            float4 a = *(const float4*)(&As[k][4 * ty]);
            float4 b = *(const float4*)(&Bs[k][4 * tx]);
            acc[0][0] = fmaf(a.x, b.x, acc[0][0]); acc[0][1] = fmaf(a.x, b.y, acc[0][1]);
            acc[0][2] = fmaf(a.x, b.z, acc[0][2]); acc[0][3] = fmaf(a.x, b.w, acc[0][3]);
            acc[1][0] = fmaf(a.y, b.x, acc[1][0]); acc[1][1] = fmaf(a.y, b.y, acc[1][1]);
            acc[1][2] = fmaf(a.y, b.z, acc[1][2]); acc[1][3] = fmaf(a.y, b.w, acc[1][3]);
            acc[2][0] = fmaf(a.z, b.x, acc[2][0]); acc[2][1] = fmaf(a.z, b.y, acc[2][1]);
            acc[2][2] = fmaf(a.z, b.z, acc[2][2]); acc[2][3] = fmaf(a.z, b.w, acc[2][3]);
            acc[3][0] = fmaf(a.w, b.x, acc[3][0]); acc[3][1] = fmaf(a.w, b.y, acc[3][1]);
            acc[3][2] = fmaf(a.w, b.z, acc[3][2]); acc[3][3] = fmaf(a.w, b.w, acc[3][3]);
        }
    }

    #pragma unroll
    for (int i = 0; i < 4; i++) {
        float4 v = make_float4(acc[i][0], acc[i][1], acc[i][2], acc[i][3]);
        *(float4*)(g_U + (t0 + 4 * ty + i) * N_RES + n0 + 4 * tx) = v;
    }
}

// ---------------------------------------------------------------------------
// Kernel 2: persistent recurrence == R14's proven kernel (acquire-spin
// detect — NO per-step fence: gpu-scope fences emit CCTL.IVALL / L1D flush,
// the measured cause of the R12/R13/R15 regressions) with ONE change:
// shfl-free publish — after the butterfly every lane holds the full dot
// pair, so lanes 0..7 each compute BOTH erfs (SIMT-predicated, same
// instruction count as 2 lanes) and store their own x8 copy directly.
// Sync topology: 128 arrivals/step, 128 acquire-spin pollers, everyone else
// parked at bar.sync — measured optimal across R7..R15.
// ---------------------------------------------------------------------------
__global__ void __launch_bounds__(NTHREADS, 1) esn_recur_kernel(
    const float* __restrict__ wres, float* __restrict__ out)
{
    __shared__ u64 red[NPAIR * NTHREADS];   // 16 KB reduction staging
    __shared__ unsigned s_cbase;

    const int tid = threadIdx.x;
    const int bid = blockIdx.x;
    const int r0  = bid * ROWS_PER_BLK;
    const int c0  = tid * CPT;
    const int wp  = tid >> 5, ln = tid & 31;
    const int mycopy = bid >> 4;            // 16 blocks share each copy

    // Load W_res slice: w[p][c] = {W[r0+2p][c0+c], W[r0+2p+1][c0+c]}
    u64 w[NPAIR][CPT];
    #pragma unroll
    for (int p = 0; p < NPAIR; p++) {
        const float4* ra = (const float4*)(wres + (r0 + 2 * p)     * N_RES + c0);
        const float4* rb = (const float4*)(wres + (r0 + 2 * p + 1) * N_RES + c0);
        float4 a0 = ra[0], a1 = ra[1];
        float4 b0 = rb[0], b1 = rb[1];
        w[p][0] = pack2(a0.x, b0.x); w[p][1] = pack2(a0.y, b0.y);
        w[p][2] = pack2(a0.z, b0.z); w[p][3] = pack2(a0.w, b0.w);
        w[p][4] = pack2(a1.x, b1.x); w[p][5] = pack2(a1.y, b1.y);
        w[p][6] = pack2(a1.z, b1.z); w[p][7] = pack2(a1.w, b1.w);
    }

    // Snapshot the quiescent step-counter; init barrier ensures agreement
    // before any arrival.
    if (tid == 0) {
        unsigned c;
        asm volatile("ld.relaxed.gpu.global.u32 %0, [%1];" : "=r"(c) : "l"(&g_scount) : "memory");
        s_cbase = c;
    }
    unsigned e0;
    asm volatile("ld.acquire.gpu.global.u32 %0, [%1];" : "=r"(e0) : "l"(&g_epoch) : "memory");
    grid_barrier(tid, e0 + 1);
    const unsigned cbase = s_cbase;

    // Step 0: lanes 0..7 each compute both row values; lane ln stores copy ln.
    if (ln < NCOPY) {
        float v0 = erff(g_U[r0 + 2 * wp])     * INV_SQRT_N;
        float v1 = erff(g_U[r0 + 2 * wp + 1]) * INV_SQRT_N;
        u64 pair = pack2(v0, v1);
        *(u64*)(g_x8 + ln * N_RES + r0 + 2 * wp) = pair;   // slot 0
        if (ln == 0)
            *(u64*)(out + r0 + 2 * wp) = pair;
    }
    __syncthreads();   // all stores happen-before tid0's release-arrival
    if (tid == 0)
        asm volatile("red.release.gpu.global.add.u32 [%0], %1;"
                     :: "l"(&g_scount), "r"(1u) : "memory");

    #pragma unroll 1
    for (int t = 1; t < T_STEPS; t++) {
        // Prefetch U[t] for my rows (lanes 0..7, warp-uniform addresses).
        float u0 = 0.f, u1 = 0.f;
        if (ln < NCOPY) {
            u0 = __ldg(&g_U[t * N_RES + r0 + 2 * wp]);
            u1 = __ldg(&g_U[t * N_RES + r0 + 2 * wp + 1]);
        }

        // R8/R14's proven barrier wait: tid0 acquire-spin, bar broadcasts.
        // (Acquire loads synchronize WITHOUT the L1D-flushing fence.)
        if (tid == 0) {
            const unsigned tgt = cbase + (unsigned)(GBLK * t);
            unsigned cur;
            do {
                asm volatile("ld.acquire.gpu.global.u32 %0, [%1];"
                             : "=r"(cur) : "l"(&g_scount) : "memory");
            } while ((int)(cur - tgt) < 0);
        }
        __syncthreads();   // acquire happens-before all lanes' loads

        // Load my 8 x values from MY copy of the previous x row (L1 bypass).
        const float4* xp = (const float4*)(g_x8 + ((t - 1) & 1) * (NCOPY * N_RES)
                                                + mycopy * N_RES + c0);
        float4 xv0 = __ldcg(xp);
        float4 xv1 = __ldcg(xp + 1);
        u64 xx[CPT];
        xx[0] = pack2(xv0.x, xv0.x); xx[1] = pack2(xv0.y, xv0.y);
        xx[2] = pack2(xv0.z, xv0.z); xx[3] = pack2(xv0.w, xv0.w);
        xx[4] = pack2(xv1.x, xv1.x); xx[5] = pack2(xv1.y, xv1.y);
        xx[6] = pack2(xv1.z, xv1.z); xx[7] = pack2(xv1.w, xv1.w);

        u64 acc[NPAIR];
        #pragma unroll
        for (int p = 0; p < NPAIR; p++) acc[p] = 0ULL;
        #pragma unroll
        for (int c = 0; c < CPT; c++) {
            #pragma unroll
            for (int p = 0; p < NPAIR; p++) fma2(acc[p], w[p][c], xx[c]);
        }

        // Stage partials; warp wp reduces row-pair wp across 256 threads.
        #pragma unroll
        for (int p = 0; p < NPAIR; p++) red[p * NTHREADS + tid] = acc[p];
        __syncthreads();

        u64 s = red[wp * NTHREADS + ln];
        #pragma unroll
        for (int k = 1; k < 8; k++) s = add2(s, red[wp * NTHREADS + ln + 32 * k]);
        #pragma unroll
        for (int m = 16; m >= 1; m >>= 1) s = add2(s, shfl_xor64(s, m));
        // Every lane now holds the full {row 2wp, row 2wp+1} dot-product pair.

        // Shfl-free publish: lanes 0..7 each compute BOTH erfs and store
        // their own x8 copy; lane 0 also stores the output row pair.
        if (ln < NCOPY) {
            float lo, hi; unpack2(s, lo, hi);
            float v0 = erff(u0 + lo) * INV_SQRT_N;
            float v1 = erff(u1 + hi) * INV_SQRT_N;
            u64 pair = pack2(v0, v1);
            *(u64*)(g_x8 + (t & 1) * (NCOPY * N_RES) + ln * N_RES + r0 + 2 * wp) = pair;
            if (ln == 0)
                *(u64*)(out + t * N_RES + r0 + 2 * wp) = pair;
        }
        __syncthreads();   // all stores done + red[] safe; HB to tid0 arrival

        if (tid == 0)
            asm volatile("red.release.gpu.global.add.u32 [%0], %1;"
                         :: "l"(&g_scount), "r"(1u) : "memory");
    }
}

// ---------------------------------------------------------------------------
extern "C" void kernel_launch(void* const* d_in, const int* in_sizes, int n_in,
                              void* d_out, int out_size)
{
    const float* input = (const float*)d_in[0];   // (2048, 128)
    const float* w_in  = (const float*)d_in[1];   // (2048, 128)
    const float* w_res = (const float*)d_in[2];   // (2048, 2048)
    float* out = (float*)d_out;                   // (2048, 2048)

    u_gemm_kernel<<<dim3(N_RES / 64, T_STEPS / 64), 256>>>(input, w_in);
    esn_recur_kernel<<<GBLK, NTHREADS>>>(w_res, out);
}